// round 3
// baseline (speedup 1.0000x reference)
#include <cuda_runtime.h>

#define SZ 256
#define NCH 8
#define NPIX (SZ*SZ)
#define WPR (SZ/32)   // words per row = 8

// Per-channel occupancy bitmasks: 8 channels x 256 rows x 8 words = 64KB
__device__ unsigned int g_maskbits[NCH * SZ * WPR];

__global__ void build_masks_kernel(const int* __restrict__ lookup) {
    int y = blockIdx.x;
    int x = threadIdx.x;
    int v = lookup[y * SZ + x];
    int w = x >> 5;
    #pragma unroll
    for (int c = 0; c < NCH; ++c) {
        unsigned int mk = __ballot_sync(0xFFFFFFFFu, v == c + 1);
        if ((x & 31) == 0)
            g_maskbits[(c * SZ + y) * WPR + w] = mk;
    }
}

__global__ __launch_bounds__(256) void knn_fill_kernel(
    const float* __restrict__ img, const int* __restrict__ lookup,
    float* __restrict__ out)
{
    const int c  = blockIdx.y;   // channel 0..7
    const int y0 = blockIdx.x;   // row
    const int x0 = threadIdx.x;  // col

    __shared__ unsigned int m[SZ * WPR];  // 8KB channel bitmask
    #pragma unroll
    for (int i = 0; i < 8; ++i)
        m[i * 256 + threadIdx.x] = g_maskbits[c * SZ * WPR + i * 256 + threadIdx.x];
    __syncthreads();

    const int pix = y0 * SZ + x0;
    const float self = __ldg(&img[pix]);

    if (__ldg(&lookup[pix]) == c + 1) {
        out[c * NPIX + pix] = self;   // filled pixel keeps its value
        return;
    }

    // Top-4 keys: (d2 << 16) | flat_idx, ascending == top_k order (ties -> lower idx)
    unsigned long long b0 = ~0ULL, b1 = ~0ULL, b2 = ~0ULL, b3 = ~0ULL;
    int found = 0;

    auto visit = [&](int yy, int xx) {
        if ((unsigned)yy >= SZ || (unsigned)xx >= SZ) return;
        unsigned int word = m[yy * WPR + (xx >> 5)];
        if ((word >> (xx & 31)) & 1u) {
            int dy = yy - y0, dx = xx - x0;
            unsigned int d2 = (unsigned int)(dy * dy + dx * dx);
            unsigned long long key =
                ((unsigned long long)d2 << 16) | (unsigned int)(yy * SZ + xx);
            ++found;
            if (key < b3) {
                b3 = key;
                if (b3 < b2) {
                    unsigned long long t = b2; b2 = b3; b3 = t;
                    if (b2 < b1) {
                        t = b1; b1 = b2; b2 = t;
                        if (b1 < b0) { t = b0; b0 = b1; b1 = t; }
                    }
                }
            }
        }
    };

    // Expanding Chebyshev rings. Candidates at ring r have d2 >= r*r, so once
    // we hold 4 and r*r > d2_4th (strict, preserving tie-break correctness),
    // no future candidate can enter the top-4.
    for (int r = 1; r < SZ; ++r) {
        if (found >= 4 && (unsigned int)(r * r) > (unsigned int)(b3 >> 16)) break;
        int yt = y0 - r, yb = y0 + r;
        for (int xx = x0 - r; xx <= x0 + r; ++xx) {
            visit(yt, xx);
            visit(yb, xx);
        }
        int xl = x0 - r, xr = x0 + r;
        for (int yy = y0 - r + 1; yy <= y0 + r - 1; ++yy) {
            visit(yy, xl);
            visit(yy, xr);
        }
    }

    // Weighted by distance (as in reference), in top_k order.
    unsigned long long keys[4] = { b0, b1, b2, b3 };
    float num = 0.0f, den = 0.0f;
    #pragma unroll
    for (int i = 0; i < 4; ++i) {
        unsigned int idx = (unsigned int)(keys[i] & 0xFFFFu);
        unsigned int d2  = (unsigned int)(keys[i] >> 16);
        float dist = sqrtf((float)d2) * (1.0f / 256.0f);  // == sqrt(d2/65536) exactly
        num += __ldg(&img[idx]) * dist;
        den += dist;
    }
    out[c * NPIX + pix] = num / den;
}

extern "C" void kernel_launch(void* const* d_in, const int* in_sizes, int n_in,
                              void* d_out, int out_size) {
    const float* coded  = (const float*)d_in[0];   // [1,1,256,256]
    const int*   lookup = (const int*)d_in[1];     // [256,256]
    float* out = (float*)d_out;                    // [1,8,256,256]

    build_masks_kernel<<<SZ, SZ>>>(lookup);
    dim3 grid(SZ, NCH);
    knn_fill_kernel<<<grid, SZ>>>(coded, lookup, out);
}

// round 4
// speedup vs baseline: 1.4863x; 1.4863x over previous
#include <cuda_runtime.h>

#define SZ 256
#define NCH 8
#define NPIX (SZ*SZ)
#define WPR (SZ/32)   // words per row = 8

// Per-channel occupancy bitmasks (row-major and column-major): 2 x 64KB
__device__ unsigned int g_maskbits [NCH * SZ * WPR];
__device__ unsigned int g_tmaskbits[NCH * SZ * WPR];

__global__ void build_masks_kernel(const int* __restrict__ lookup) {
    int y = blockIdx.x;
    int x = threadIdx.x;
    int v = lookup[y * SZ + x];
    int w = x >> 5;
    #pragma unroll
    for (int c = 0; c < NCH; ++c) {
        unsigned int mk = __ballot_sync(0xFFFFFFFFu, v == c + 1);
        if ((x & 31) == 0)
            g_maskbits[(c * SZ + y) * WPR + w] = mk;
    }
}

// Transpose the bitmasks: one warp per (channel, x, word_y)
__global__ void build_tmasks_kernel() {
    int gw   = (blockIdx.x * blockDim.x + threadIdx.x) >> 5;
    int lane = threadIdx.x & 31;
    int c    = gw >> 11;          // 2048 warps per channel
    int rem  = gw & 2047;
    int x    = rem >> 3;
    int wy   = rem & 7;
    int yy   = (wy << 5) + lane;
    unsigned int bit = (g_maskbits[(c * SZ + yy) * WPR + (x >> 5)] >> (x & 31)) & 1u;
    unsigned int mk  = __ballot_sync(0xFFFFFFFFu, bit);
    if (lane == 0)
        g_tmaskbits[(c * SZ + x) * WPR + wy] = mk;
}

__global__ __launch_bounds__(256) void knn_fill_kernel(
    const float* __restrict__ img, const int* __restrict__ lookup,
    float* __restrict__ out)
{
    const int c  = blockIdx.y;   // channel 0..7
    const int y0 = blockIdx.x;   // row
    const int x0 = threadIdx.x;  // col

    __shared__ unsigned int m [SZ * WPR];  // row-major channel bitmask (8KB)
    __shared__ unsigned int mt[SZ * WPR];  // column-major channel bitmask (8KB)
    #pragma unroll
    for (int i = 0; i < 8; ++i) {
        m [i * 256 + threadIdx.x] = g_maskbits [c * SZ * WPR + i * 256 + threadIdx.x];
        mt[i * 256 + threadIdx.x] = g_tmaskbits[c * SZ * WPR + i * 256 + threadIdx.x];
    }
    __syncthreads();

    const int pix = y0 * SZ + x0;
    const float self = __ldg(&img[pix]);

    if (__ldg(&lookup[pix]) == c + 1) {
        out[c * NPIX + pix] = self;   // filled pixel keeps its value
        return;
    }

    // Top-4 keys: (d2 << 16) | flat_idx, ascending == top_k order (ties -> lower idx)
    unsigned long long b0 = ~0ULL, b1 = ~0ULL, b2 = ~0ULL, b3 = ~0ULL;

    auto insert = [&](unsigned long long key) {
        if (key < b3) {
            b3 = key;
            if (b3 < b2) {
                unsigned long long t = b2; b2 = b3; b3 = t;
                if (b2 < b1) {
                    t = b1; b1 = b2; b2 = t;
                    if (b1 < b0) { t = b0; b0 = b1; b1 = t; }
                }
            }
        }
    };

    // Scan bits x in [lo,hi] of row yy (word-parallel over the row-major mask)
    auto scan_row = [&](int yy, int lo, int hi) {
        if ((unsigned)yy >= SZ) return;
        lo = lo < 0 ? 0 : lo;
        hi = hi > SZ - 1 ? SZ - 1 : hi;
        const int dy2 = (yy - y0) * (yy - y0);
        const int wlo = lo >> 5, whi = hi >> 5;
        const unsigned int mlo = 0xFFFFFFFFu << (lo & 31);
        const unsigned int mhi = 0xFFFFFFFFu >> (31 - (hi & 31));
        const unsigned int* row = &m[yy << 3];
        const unsigned int idxb = (unsigned int)(yy << 8);
        for (int w = wlo; w <= whi; ++w) {
            unsigned int word = row[w];
            if (w == wlo) word &= mlo;
            if (w == whi) word &= mhi;
            int xb = w << 5;
            while (word) {
                int b = __ffs(word) - 1;
                word &= word - 1;
                int dx = xb + b - x0;
                unsigned int d2 = (unsigned int)(dx * dx + dy2);
                insert(((unsigned long long)d2 << 16) | (idxb + xb + b));
            }
        }
    };

    // Scan bits y in [lo,hi] of column xx (word-parallel over the transposed mask)
    auto scan_col = [&](int xx, int lo, int hi) {
        if ((unsigned)xx >= SZ) return;
        lo = lo < 0 ? 0 : lo;
        hi = hi > SZ - 1 ? SZ - 1 : hi;
        if (lo > hi) return;
        const int dx2 = (xx - x0) * (xx - x0);
        const int wlo = lo >> 5, whi = hi >> 5;
        const unsigned int mlo = 0xFFFFFFFFu << (lo & 31);
        const unsigned int mhi = 0xFFFFFFFFu >> (31 - (hi & 31));
        const unsigned int* col = &mt[xx << 3];
        for (int w = wlo; w <= whi; ++w) {
            unsigned int word = col[w];
            if (w == wlo) word &= mlo;
            if (w == whi) word &= mhi;
            int yb = w << 5;
            while (word) {
                int b = __ffs(word) - 1;
                word &= word - 1;
                int yy = yb + b;
                int dy = yy - y0;
                unsigned int d2 = (unsigned int)(dy * dy + dx2);
                insert(((unsigned long long)d2 << 16) |
                       (unsigned int)((yy << 8) + xx));
            }
        }
    };

    // Expanding Chebyshev rings. Candidates at ring r have d2 >= r*r, so once
    // we hold 4 and r*r > d2_4th (strict, preserving tie-break correctness),
    // no future candidate can enter the top-4. Within a ring, prune segments
    // to |offset| <= floor(sqrt(d2_4 - r^2)) (inclusive, so equal-d2 ties kept).
    for (int r = 1; r < SZ; ++r) {
        int wx = r;
        if (b3 != ~0ULL) {
            unsigned int lim = (unsigned int)(b3 >> 16);
            if ((unsigned int)(r * r) > lim) break;
            int rem = (int)lim - r * r;               // >= 0 here
            int u = __float2int_rd(sqrtf((float)rem));
            if ((u + 1) * (u + 1) <= rem) ++u;        // exact floor(sqrt(rem))
            if (u * u > rem) --u;
            wx = u < r ? u : r;                        // clamp: stay on this ring
        }
        scan_row(y0 - r, x0 - wx, x0 + wx);
        scan_row(y0 + r, x0 - wx, x0 + wx);
        int cl = y0 - r + 1, ch = y0 + r - 1;
        int wl = cl > y0 - wx ? cl : y0 - wx;
        int wh = ch < y0 + wx ? ch : y0 + wx;
        scan_col(x0 - r, wl, wh);
        scan_col(x0 + r, wl, wh);
    }

    // Weighted by distance (as in reference), in top_k order.
    unsigned long long keys[4] = { b0, b1, b2, b3 };
    float num = 0.0f, den = 0.0f;
    #pragma unroll
    for (int i = 0; i < 4; ++i) {
        unsigned int idx = (unsigned int)(keys[i] & 0xFFFFu);
        unsigned int d2  = (unsigned int)(keys[i] >> 16);
        float dist = sqrtf((float)d2) * (1.0f / 256.0f);  // == sqrt(d2/65536) exactly
        num += __ldg(&img[idx]) * dist;
        den += dist;
    }
    out[c * NPIX + pix] = num / den;
}

extern "C" void kernel_launch(void* const* d_in, const int* in_sizes, int n_in,
                              void* d_out, int out_size) {
    const float* coded  = (const float*)d_in[0];   // [1,1,256,256]
    const int*   lookup = (const int*)d_in[1];     // [256,256]
    float* out = (float*)d_out;                    // [1,8,256,256]

    build_masks_kernel<<<SZ, SZ>>>(lookup);
    build_tmasks_kernel<<<NCH * SZ * WPR / 8, 256>>>();   // 2048 blocks, warp/word
    dim3 grid(SZ, NCH);
    knn_fill_kernel<<<grid, SZ>>>(coded, lookup, out);
}